// round 4
// baseline (speedup 1.0000x reference)
#include <cuda_runtime.h>
#include <cstddef>

// DotMatrix on GB300 (sm_103a).
// out[b,i,j,t,c] = complex dot over m of A_i with SO3-conjugated A_j,
// concatenated over ell in {0..3} (M = 2*ell+1), tau = 32 per ell.
//
// Identity 1 (fold): sum_m A_i[m]*sign(m)*A_j[M-1-m]
//                  == sum_m (sign(m)*A_i[M-1-m]) * A_j[m]
// Identity 2 (symmetry): out[b,i,j,:] == out[b,j,i,:] (both components)
//   -> compute upper-triangular tile pairs only, mirror-store the rest.
//
// R4: ell split into the grid (1 barrier phase/block, 4x blocks),
// launch_bounds(256,5) for ~62% occupancy; heavy ells scheduled first.

namespace cfg {
constexpr int kN = 256;
constexpr int kT = 32;                    // taus per ell
constexpr int JT = 16;
constexpr int IT = 16;                    // = TY * KI
constexpr int KI = 2;
constexpr int TY = 8;
constexpr int NT = 32 * TY;               // 256 threads
constexpr int NB = kN / JT;               // 16
constexpr int NPAIRS = NB * (NB + 1) / 2; // 136
constexpr int SHF = JT * kT * 7 * 2;      // 7168 floats = 28KB (ell=3 size)
}

template <int ELL>
__device__ __forceinline__ void doEll(const float* __restrict__ rep,
                                      float* __restrict__ sh,
                                      int b, int i0, int j0,
                                      int tau, int ty, int tid, bool mirror,
                                      float2* __restrict__ out) {
  using namespace cfg;
  constexpr int M = 2 * ELL + 1;

  // ---- raw coalesced copy of B tile: sh[(jl*32+tau)*2M + 2m + c]
  {
    const float4* src = reinterpret_cast<const float4*>(
        rep + (size_t)(b * kN + j0) * (kT * M * 2));
    float4* dst = reinterpret_cast<float4*>(sh);
#pragma unroll
    for (int k = 0; k < M; ++k)            // exactly M rounds of 256 threads
      dst[tid + k * NT] = src[tid + k * NT];
  }

  // ---- A with flip+sign folded, KI i-rows, this thread's tau
  float ar[KI][M], ai[KI][M];
#pragma unroll
  for (int ki = 0; ki < KI; ++ki) {
    int i = i0 + ty + ki * TY;
    const float2* ab = reinterpret_cast<const float2*>(rep) +
                       (size_t)((b * kN + i) * kT + tau) * M;
#pragma unroll
    for (int m = 0; m < M; ++m) {
      float2 v = __ldg(&ab[M - 1 - m]);
      float s = ((m + ELL) & 1) ? -1.0f : 1.0f;
      ar[ki][m] = s * v.x;
      ai[ki][m] = s * v.y;
    }
  }
  __syncthreads();

#pragma unroll 4
  for (int jl = 0; jl < JT; ++jl) {
    const float2* bp =
        reinterpret_cast<const float2*>(sh) + (jl * kT + tau) * M;
    float a1[KI], a2[KI], ci[KI];
#pragma unroll
    for (int ki = 0; ki < KI; ++ki) { a1[ki] = 0.f; a2[ki] = 0.f; ci[ki] = 0.f; }
#pragma unroll
    for (int m = 0; m < M; ++m) {
      float2 bv = bp[m];                   // conflict-free LDS.64 (checked)
#pragma unroll
      for (int ki = 0; ki < KI; ++ki) {
        a1[ki] = fmaf(ar[ki][m], bv.x, a1[ki]);
        a2[ki] = fmaf(ai[ki][m], bv.y, a2[ki]);
        ci[ki] = fmaf(ar[ki][m], bv.y, ci[ki]);
        ci[ki] = fmaf(ai[ki][m], bv.x, ci[ki]);
      }
    }
    int j = j0 + jl;
#pragma unroll
    for (int ki = 0; ki < KI; ++ki) {
      int i = i0 + ty + ki * TY;
      float2 val = make_float2(a1[ki] - a2[ki], ci[ki]);
      size_t o1 = ((size_t)((b * kN + i) * kN + j)) * 128 + ELL * kT + tau;
      __stcs(&out[o1], val);
      if (mirror) {
        size_t o2 = ((size_t)((b * kN + j) * kN + i)) * 128 + ELL * kT + tau;
        __stcs(&out[o2], val);
      }
    }
  }
}

__global__ void __launch_bounds__(cfg::NT, 5)
dotmat_kernel(const float* __restrict__ r0, const float* __restrict__ r1,
              const float* __restrict__ r2, const float* __restrict__ r3,
              float2* __restrict__ out) {
  using namespace cfg;
  __shared__ float sh[SHF];
  const int tau = threadIdx.x;
  const int ty  = threadIdx.y;
  const int tid = ty * 32 + tau;
  const int b   = blockIdx.y;

  // blockIdx.x encodes (pair, ell); heavy ells first in launch order.
  const int px  = blockIdx.x;
  const int ell = 3 - (px & 3);
  const int p   = px >> 2;

  // decode upper-triangular pair index p -> (bi, bj), bi <= bj
  int bi = (int)((33.0f - sqrtf(1089.0f - 8.0f * (float)p)) * 0.5f);
  while ((bi + 1) * (33 - (bi + 1)) / 2 <= p) ++bi;
  while (bi * (33 - bi) / 2 > p) --bi;
  const int bj = bi + (p - bi * (33 - bi) / 2);

  const int i0 = bi * IT;
  const int j0 = bj * JT;
  const bool mirror = (bi != bj);

  switch (ell) {
    case 0: doEll<0>(r0, sh, b, i0, j0, tau, ty, tid, mirror, out); break;
    case 1: doEll<1>(r1, sh, b, i0, j0, tau, ty, tid, mirror, out); break;
    case 2: doEll<2>(r2, sh, b, i0, j0, tau, ty, tid, mirror, out); break;
    default: doEll<3>(r3, sh, b, i0, j0, tau, ty, tid, mirror, out); break;
  }
}

extern "C" void kernel_launch(void* const* d_in, const int* in_sizes, int n_in,
                              void* d_out, int out_size) {
  (void)in_sizes; (void)n_in; (void)out_size;
  dim3 grid(cfg::NPAIRS * 4, 2);   // (pair, ell) x batch
  dim3 block(32, cfg::TY);
  dotmat_kernel<<<grid, block>>>(
      (const float*)d_in[0], (const float*)d_in[1],
      (const float*)d_in[2], (const float*)d_in[3],
      (float2*)d_out);
}